// round 1
// baseline (speedup 1.0000x reference)
#include <cuda_runtime.h>
#include <cstdint>
#include <cstddef>

#define NB 8
#define NL 512
#define ND 512
#define NH 8
#define HD 64
#define NE 4
#define NDF 2048
#define NBL 4096   // NB*NL

#define NEGINF __int_as_float(0xff800000)

// ---------------- scratch (static device allocations) ----------------
__device__ float g_h [NBL*ND];
__device__ float g_t [NBL*ND];
__device__ float g_q [NBL*ND];
__device__ float g_k [NBL*ND];
__device__ float g_v [NBL*ND];
__device__ float g_ao[NBL*ND];
__device__ float g_mid[NBL*NDF];
__device__ float g_sc[(size_t)64*NL*NL];     // [B*H][L][L]
__device__ float g_cw[NE*3*ND*ND];           // conv weights transposed [l][k][i][o]

// ---------------- conv weight transpose: w[l][o][i][k] -> w2[l][k][i][o] ----------------
__global__ void tconv_kernel(const float* __restrict__ w, float* __restrict__ o) {
    int idx = blockIdx.x * 256 + threadIdx.x;        // total 4*3*512*512
    int l  = idx / (3*ND*ND);
    int r  = idx % (3*ND*ND);
    int k  = r / (ND*ND);
    int r2 = r % (ND*ND);
    int i  = r2 / ND;
    int oo = r2 % ND;
    o[idx] = w[(((size_t)l*ND + oo)*ND + i)*3 + k];
}

// ---------------- input embedding ----------------
__global__ __launch_bounds__(256) void embed_kernel(
    const float* __restrict__ x, const float* __restrict__ tf,
    const float* __restrict__ inw, const float* __restrict__ inb,
    const float* __restrict__ pe, const float* __restrict__ tw,
    const float* __restrict__ tb, const float* __restrict__ ps,
    const float* __restrict__ ts, float* __restrict__ out)
{
    int bl = blockIdx.x;
    int t  = threadIdx.x;
    __shared__ float xs[64];
    __shared__ float t2[2];
    if (t < 64) xs[t] = x[bl*64 + t];
    if (t < 2)  t2[t] = tf[bl*2 + t];
    __syncthreads();
    float pss = ps[0], tss = ts[0];
    int pos = bl & (NL-1);
    #pragma unroll
    for (int rep = 0; rep < 2; rep++) {
        int d = t + (rep << 8);
        float acc = inb[d];
        #pragma unroll 16
        for (int i = 0; i < 64; i++) acc += xs[i] * inw[i*ND + d];
        acc += pss * pe[pos*ND + d];
        acc += tss * (t2[0]*tw[d] + t2[1]*tw[ND + d] + tb[d]);
        out[bl*ND + d] = acc;
    }
}

// ---------------- generic tiled GEMM (M=4096 fixed), 64x64x16, 4x4 per thread ----------------
// C[m,n] = sum_k A[m,k]*B[k,n] + bias[n]  (+relu) (+res[m,n])
// CONV: A addressing becomes causal-conv gather from g_h-style [4096,512] buffer.
template<int CONV, int RELU, int ADDRES>
__global__ __launch_bounds__(256) void gemm_kernel(
    const float* __restrict__ A, const float* __restrict__ Bm,
    const float* __restrict__ bias, const float* __restrict__ res,
    float* __restrict__ C, int N, int K)
{
    __shared__ __align__(16) float As[16][64];
    __shared__ __align__(16) float Bs[16][64];

    int bn = blockIdx.x << 6;
    int bm = blockIdx.y << 6;
    int t  = threadIdx.x;
    int tx = t & 15, ty = t >> 4;

    int aRow = t >> 2;            // 0..63
    int aCol = (t & 3) << 2;      // 0,4,8,12
    int bRow = ty;                // 0..15
    int bCol = tx << 2;           // 0..60

    float acc[4][4] = {};
    int nk = K >> 4;

    for (int kt = 0; kt < nk; kt++) {
        int k0 = kt << 4;
        float4 av;
        if (CONV) {
            int kk   = k0 + aCol;
            int kidx = kk >> 9;           // which tap 0..2
            int ii   = kk & 511;          // channel
            int m    = bm + aRow;
            int tt   = m & 511;           // time within batch
            int sh   = kidx - 2;
            if (tt + sh >= 0) av = *(const float4*)&A[(size_t)(m + sh)*512 + ii];
            else              av = make_float4(0.f, 0.f, 0.f, 0.f);
        } else {
            av = *(const float4*)&A[(size_t)(bm + aRow)*K + k0 + aCol];
        }
        float4 bv = *(const float4*)&Bm[(size_t)(k0 + bRow)*N + bn + bCol];

        As[aCol+0][aRow] = av.x;
        As[aCol+1][aRow] = av.y;
        As[aCol+2][aRow] = av.z;
        As[aCol+3][aRow] = av.w;
        *(float4*)&Bs[bRow][bCol] = bv;
        __syncthreads();

        #pragma unroll
        for (int kk = 0; kk < 16; kk++) {
            float4 a4 = *(const float4*)&As[kk][ty << 2];
            float4 b4 = *(const float4*)&Bs[kk][tx << 2];
            float ar[4] = {a4.x, a4.y, a4.z, a4.w};
            float br[4] = {b4.x, b4.y, b4.z, b4.w};
            #pragma unroll
            for (int i = 0; i < 4; i++)
                #pragma unroll
                for (int j = 0; j < 4; j++)
                    acc[i][j] += ar[i] * br[j];
        }
        __syncthreads();
    }

    float4 bi4 = *(const float4*)&bias[bn + (tx << 2)];
    float bb[4] = {bi4.x, bi4.y, bi4.z, bi4.w};
    #pragma unroll
    for (int i = 0; i < 4; i++) {
        int row = bm + (ty << 2) + i;
        float4 o;
        o.x = acc[i][0] + bb[0];
        o.y = acc[i][1] + bb[1];
        o.z = acc[i][2] + bb[2];
        o.w = acc[i][3] + bb[3];
        if (RELU) {
            o.x = fmaxf(o.x, 0.f); o.y = fmaxf(o.y, 0.f);
            o.z = fmaxf(o.z, 0.f); o.w = fmaxf(o.w, 0.f);
        }
        if (ADDRES) {
            float4 r4 = *(const float4*)&res[(size_t)row*N + bn + (tx << 2)];
            o.x += r4.x; o.y += r4.y; o.z += r4.z; o.w += r4.w;
        }
        *(float4*)&C[(size_t)row*N + bn + (tx << 2)] = o;
    }
}

// ---------------- fused add + LayerNorm ----------------
__global__ __launch_bounds__(256) void ln_kernel(
    const float* __restrict__ a, const float* __restrict__ b,
    const float* __restrict__ sc, const float* __restrict__ bi,
    float* __restrict__ out)
{
    int row = blockIdx.x;
    int t = threadIdx.x;
    const float* ar = a + (size_t)row*ND;
    const float* br = b + (size_t)row*ND;
    float v0 = ar[t]       + br[t];
    float v1 = ar[t + 256] + br[t + 256];
    float s1 = v0 + v1;
    float s2 = v0*v0 + v1*v1;
    #pragma unroll
    for (int off = 16; off > 0; off >>= 1) {
        s1 += __shfl_xor_sync(0xffffffffu, s1, off);
        s2 += __shfl_xor_sync(0xffffffffu, s2, off);
    }
    __shared__ float r1[8], r2[8], mv[2];
    int w = t >> 5, lane = t & 31;
    if (lane == 0) { r1[w] = s1; r2[w] = s2; }
    __syncthreads();
    if (t == 0) {
        float a1 = 0.f, a2 = 0.f;
        #pragma unroll
        for (int i = 0; i < 8; i++) { a1 += r1[i]; a2 += r2[i]; }
        float mean = a1 * (1.f/512.f);
        float var  = a2 * (1.f/512.f) - mean*mean;
        mv[0] = mean;
        mv[1] = rsqrtf(var + 1e-5f);
    }
    __syncthreads();
    float mean = mv[0], rstd = mv[1];
    out[(size_t)row*ND + t]       = (v0 - mean)*rstd*sc[t]       + bi[t];
    out[(size_t)row*ND + t + 256] = (v1 - mean)*rstd*sc[t + 256] + bi[t + 256];
}

// ---------------- scores: per (b,h), lower-triangular 64x64 tiles of q @ k^T * scale --------
__global__ __launch_bounds__(256) void scores_kernel(
    const float* __restrict__ q, const float* __restrict__ k, float* __restrict__ sc)
{
    int nt = blockIdx.x, mt = blockIdx.y, bh = blockIdx.z;
    if (nt > mt) return;
    int b = bh >> 3, h = bh & 7;
    __shared__ float Qs[64*65];
    __shared__ float Ks[64*65];
    int t = threadIdx.x;
    const float* qb = q + ((size_t)(b*NL + mt*64))*ND + h*HD;
    const float* kb = k + ((size_t)(b*NL + nt*64))*ND + h*HD;
    #pragma unroll
    for (int i = 0; i < 16; i++) {
        int lin = t + (i << 8);
        int r = lin >> 6, d = lin & 63;
        Qs[r*65 + d] = qb[(size_t)r*ND + d];
        Ks[r*65 + d] = kb[(size_t)r*ND + d];
    }
    __syncthreads();
    int tx = t & 15, ty = t >> 4;
    float acc[4][4] = {};
    #pragma unroll 4
    for (int d = 0; d < 64; d++) {
        float ar[4], br[4];
        #pragma unroll
        for (int i = 0; i < 4; i++) ar[i] = Qs[((ty<<2)+i)*65 + d];
        #pragma unroll
        for (int j = 0; j < 4; j++) br[j] = Ks[((tx<<2)+j)*65 + d];
        #pragma unroll
        for (int i = 0; i < 4; i++)
            #pragma unroll
            for (int j = 0; j < 4; j++)
                acc[i][j] += ar[i]*br[j];
    }
    float* base = sc + (size_t)bh*NL*NL;
    #pragma unroll
    for (int i = 0; i < 4; i++) {
        int m = mt*64 + (ty<<2) + i;
        float4 o;
        o.x = acc[i][0]*0.125f; o.y = acc[i][1]*0.125f;
        o.z = acc[i][2]*0.125f; o.w = acc[i][3]*0.125f;
        *(float4*)&base[(size_t)m*NL + nt*64 + (tx<<2)] = o;
    }
}

// ---------------- top-k(256) select + softmax + P@V -----------------
// block = (qtile of 32 rows, bh). 256 threads, 8 warps, each warp owns 4 rows.
// dyn smem: p[32][512] (64KB) + vt[64][64] (16KB) = 80KB
__global__ __launch_bounds__(256) void attn_kernel(
    const float* __restrict__ sc, const float* __restrict__ v, float* __restrict__ ao)
{
    extern __shared__ float sm[];
    float* p  = sm;             // 32*512
    float* vt = sm + 32*512;    // 64*64
    int qt = blockIdx.x, bh = blockIdx.y;
    int b = bh >> 3, h = bh & 7;
    int t = threadIdx.x;

    // load 32 score rows
    const float4* s4 = (const float4*)(sc + (size_t)bh*NL*NL + (size_t)(qt*32)*NL);
    float4* p4 = (float4*)p;
    #pragma unroll
    for (int i = 0; i < 16; i++) p4[t + (i << 8)] = s4[t + (i << 8)];
    __syncthreads();

    int w = t >> 5, lane = t & 31;
    for (int rr = 0; rr < 4; rr++) {
        int r  = (w << 2) + rr;
        int qg = (qt << 5) + r;
        int nv = qg + 1;                       // valid prefix length
        float    ev[16];
        unsigned uv[16];
        float    svv[16];
        #pragma unroll
        for (int ii = 0; ii < 16; ii++) {
            int j = lane + (ii << 5);
            bool val = j < nv;
            float s = val ? p[(r << 9) + j] : NEGINF;
            svv[ii] = s;
            unsigned bits = __float_as_uint(s);
            uv[ii] = val ? ((bits & 0x80000000u) ? ~bits : (bits | 0x80000000u)) : 0u;
        }
        unsigned T = 1u;                       // nv<=256: keep every valid element
        if (nv > 256) {
            T = 0u;
            for (int bit = 31; bit >= 0; bit--) {
                unsigned cand = T | (1u << bit);
                int c = 0;
                #pragma unroll
                for (int ii = 0; ii < 16; ii++) c += (uv[ii] >= cand);
                c = __reduce_add_sync(0xffffffffu, c);
                if (c >= 256) T = cand;
            }
        }
        float m = NEGINF;
        #pragma unroll
        for (int ii = 0; ii < 16; ii++)
            if (uv[ii] >= T) m = fmaxf(m, svv[ii]);
        #pragma unroll
        for (int off = 16; off > 0; off >>= 1)
            m = fmaxf(m, __shfl_xor_sync(0xffffffffu, m, off));
        float z = 0.f;
        #pragma unroll
        for (int ii = 0; ii < 16; ii++) {
            float e = (uv[ii] >= T) ? __expf(svv[ii] - m) : 0.f;
            ev[ii] = e;
            z += e;
        }
        #pragma unroll
        for (int off = 16; off > 0; off >>= 1)
            z += __shfl_xor_sync(0xffffffffu, z, off);
        float inv = 1.f / z;
        #pragma unroll
        for (int ii = 0; ii < 16; ii++) {
            int j = lane + (ii << 5);
            p[(r << 9) + j] = ev[ii] * inv;
        }
    }
    __syncthreads();

    // P @ V
    float acc[8] = {};
    int d = t & 63, rb = t >> 6;
    for (int jt = 0; jt < 8; jt++) {
        const float4* v4 = (const float4*)(v + ((size_t)(b*NL + (jt << 6)))*ND + (h << 6));
        float4* vt4 = (float4*)vt;
        #pragma unroll
        for (int i = 0; i < 4; i++) {
            int lin = t + (i << 8);           // 0..1023 float4s
            int jr = lin >> 4, d4 = lin & 15;
            vt4[lin] = v4[(size_t)jr*128 + d4];
        }
        __syncthreads();
        #pragma unroll 2
        for (int j = 0; j < 64; j++) {
            float vv = vt[(j << 6) + d];
            int jj = (jt << 6) + j;
            #pragma unroll
            for (int i = 0; i < 8; i++)
                acc[i] += p[((rb + (i << 2)) << 9) + jj] * vv;
        }
        __syncthreads();
    }
    #pragma unroll
    for (int i = 0; i < 8; i++) {
        int row = (qt << 5) + rb + (i << 2);
        ao[((size_t)(b*NL + row))*ND + (h << 6) + d] = acc[i];
    }
}

// ---------------- launch ----------------
extern "C" void kernel_launch(void* const* d_in, const int* in_sizes, int n_in,
                              void* d_out, int out_size) {
    const float* x     = (const float*)d_in[0];
    const float* tf    = (const float*)d_in[1];
    const float* in_w  = (const float*)d_in[2];
    const float* in_b  = (const float*)d_in[3];
    const float* pe    = (const float*)d_in[4];
    const float* tw    = (const float*)d_in[5];
    const float* tb    = (const float*)d_in[6];
    const float* ps    = (const float*)d_in[7];
    const float* ts    = (const float*)d_in[8];
    const float* convw = (const float*)d_in[9];
    const float* convb = (const float*)d_in[10];
    const float* qw    = (const float*)d_in[11];
    const float* qb    = (const float*)d_in[12];
    const float* kw    = (const float*)d_in[13];
    const float* kb    = (const float*)d_in[14];
    const float* vw    = (const float*)d_in[15];
    const float* vb    = (const float*)d_in[16];
    const float* ow    = (const float*)d_in[17];
    const float* ob    = (const float*)d_in[18];
    const float* f1w   = (const float*)d_in[19];
    const float* f1b   = (const float*)d_in[20];
    const float* f2w   = (const float*)d_in[21];
    const float* f2b   = (const float*)d_in[22];
    const float* n1s   = (const float*)d_in[23];
    const float* n1b   = (const float*)d_in[24];
    const float* n2s   = (const float*)d_in[25];
    const float* n2b   = (const float*)d_in[26];

    float *h, *tbuf, *qv, *kv, *vv, *ao, *mid, *sc, *cw;
    cudaGetSymbolAddress((void**)&h,    g_h);
    cudaGetSymbolAddress((void**)&tbuf, g_t);
    cudaGetSymbolAddress((void**)&qv,   g_q);
    cudaGetSymbolAddress((void**)&kv,   g_k);
    cudaGetSymbolAddress((void**)&vv,   g_v);
    cudaGetSymbolAddress((void**)&ao,   g_ao);
    cudaGetSymbolAddress((void**)&mid,  g_mid);
    cudaGetSymbolAddress((void**)&sc,   g_sc);
    cudaGetSymbolAddress((void**)&cw,   g_cw);

    cudaFuncSetAttribute(attn_kernel, cudaFuncAttributeMaxDynamicSharedMemorySize, 81920);

    // conv weight re-layout (deterministic each call)
    tconv_kernel<<<(NE*3*ND*ND)/256, 256>>>(convw, cw);

    // input embedding
    embed_kernel<<<NBL, 256>>>(x, tf, in_w, in_b, pe, tw, tb, ps, ts, h);

    dim3 g512(ND/64, NBL/64);       // N=512
    dim3 gdf (NDF/64, NBL/64);      // N=2048

    for (int l = 0; l < NE; l++) {
        // causal conv (K = 3*512 = 1536) -> tbuf, then LN1 -> h
        gemm_kernel<1,0,0><<<g512, 256>>>(h, cw + (size_t)l*3*ND*ND, convb + l*ND,
                                          nullptr, tbuf, ND, 3*ND);
        ln_kernel<<<NBL, 256>>>(h, tbuf, n1s + l*ND, n1b + l*ND, h);

        // Q, K, V projections
        gemm_kernel<0,0,0><<<g512, 256>>>(h, qw + (size_t)l*ND*ND, qb + l*ND, nullptr, qv, ND, ND);
        gemm_kernel<0,0,0><<<g512, 256>>>(h, kw + (size_t)l*ND*ND, kb + l*ND, nullptr, kv, ND, ND);
        gemm_kernel<0,0,0><<<g512, 256>>>(h, vw + (size_t)l*ND*ND, vb + l*ND, nullptr, vv, ND, ND);

        // scores (lower-triangular tiles only)
        scores_kernel<<<dim3(8, 8, 64), 256>>>(qv, kv, sc);

        // top-k select + softmax + P@V
        attn_kernel<<<dim3(16, 64), 256, 81920>>>(sc, vv, ao);

        // output projection -> tbuf, LN2 -> h
        gemm_kernel<0,0,0><<<g512, 256>>>(ao, ow + (size_t)l*ND*ND, ob + l*ND, nullptr, tbuf, ND, ND);
        ln_kernel<<<NBL, 256>>>(h, tbuf, n2s + l*ND, n2b + l*ND, h);

        // FFN
        gemm_kernel<0,1,0><<<gdf, 256>>>(h, f1w + (size_t)l*ND*NDF, f1b + l*NDF,
                                         nullptr, mid, NDF, ND);
        float* outp = (l == NE-1) ? (float*)d_out : h;
        gemm_kernel<0,0,1><<<g512, 256>>>(mid, f2w + (size_t)l*NDF*ND, f2b + l*ND,
                                          h, outp, ND, NDF);
    }
}

// round 2
// speedup vs baseline: 1.1996x; 1.1996x over previous
#include <cuda_runtime.h>
#include <cstdint>
#include <cstddef>

#define NB 8
#define NL 512
#define ND 512
#define NH 8
#define HD 64
#define NE 4
#define NDF 2048
#define NBL 4096   // NB*NL

#define NEGINF __int_as_float(0xff800000)

// ---------------- scratch (static device allocations) ----------------
__device__ float g_h [NBL*ND];
__device__ float g_t [NBL*ND];
__device__ float g_q [NBL*ND];
__device__ float g_k [NBL*ND];
__device__ float g_v [NBL*ND];
__device__ float g_ao[NBL*ND];
__device__ float g_mid[NBL*NDF];
__device__ float g_sc[(size_t)64*NL*NL];     // [B*H][L][L]
__device__ float g_cw[NE*3*ND*ND];           // conv weights transposed [l][k][i][o]

// ---------------- conv weight transpose: w[l][o][i][k] -> w2[l][k][i][o] ----------------
__global__ void tconv_kernel(const float* __restrict__ w, float* __restrict__ o) {
    int idx = blockIdx.x * 256 + threadIdx.x;        // total 4*3*512*512
    int l  = idx / (3*ND*ND);
    int r  = idx % (3*ND*ND);
    int k  = r / (ND*ND);
    int r2 = r % (ND*ND);
    int i  = r2 / ND;
    int oo = r2 % ND;
    o[idx] = w[(((size_t)l*ND + oo)*ND + i)*3 + k];
}

// ---------------- input embedding ----------------
__global__ __launch_bounds__(256) void embed_kernel(
    const float* __restrict__ x, const float* __restrict__ tf,
    const float* __restrict__ inw, const float* __restrict__ inb,
    const float* __restrict__ pe, const float* __restrict__ tw,
    const float* __restrict__ tb, const float* __restrict__ ps,
    const float* __restrict__ ts, float* __restrict__ out)
{
    int bl = blockIdx.x;
    int t  = threadIdx.x;
    __shared__ float xs[64];
    __shared__ float t2[2];
    if (t < 64) xs[t] = x[bl*64 + t];
    if (t < 2)  t2[t] = tf[bl*2 + t];
    __syncthreads();
    float pss = ps[0], tss = ts[0];
    int pos = bl & (NL-1);
    #pragma unroll
    for (int rep = 0; rep < 2; rep++) {
        int d = t + (rep << 8);
        float acc = inb[d];
        #pragma unroll 16
        for (int i = 0; i < 64; i++) acc += xs[i] * inw[i*ND + d];
        acc += pss * pe[pos*ND + d];
        acc += tss * (t2[0]*tw[d] + t2[1]*tw[ND + d] + tb[d]);
        out[bl*ND + d] = acc;
    }
}

// ---------------- SGEMM 128x128x16, double-buffered, 8x8 per thread ----------------
// C[m,n] = sum_k A[m,k]*B[k,n] + bias[n]  (+relu) (+res[m,n])
// CONV: A addressing becomes causal-conv gather (taps along K: k = tap*512 + chan)
template<int CONV, int RELU, int ADDRES>
__global__ __launch_bounds__(256) void gemm_kernel(
    const float* __restrict__ A, const float* __restrict__ Bm,
    const float* __restrict__ bias, const float* __restrict__ res,
    float* __restrict__ C, int N, int K)
{
    __shared__ __align__(16) float As[2][16][128];
    __shared__ __align__(16) float Bs[2][16][128];

    int bn = blockIdx.x << 7;
    int bm = blockIdx.y << 7;
    int t  = threadIdx.x;
    int tx = t & 15, ty = t >> 4;

    int ar = t >> 2;             // 0..63  (A tile row within 64-row half)
    int ac = (t & 3) << 2;       // 0,4,8,12
    int br = t >> 5;             // 0..7
    int bc = (t & 31) << 2;      // 0..124

    float4 pa0, pa1, pb0, pb1;

    #define LOAD_A(k0, rowoff, dst)                                            \
        do {                                                                   \
            int m_ = bm + ar + (rowoff);                                       \
            if (CONV) {                                                        \
                int kk_ = (k0) + ac;                                           \
                int kidx_ = kk_ >> 9;                                          \
                int ii_ = kk_ & 511;                                           \
                int sh_ = kidx_ - 2;                                           \
                int tt_ = m_ & 511;                                            \
                if (tt_ + sh_ >= 0)                                            \
                    dst = *(const float4*)&A[(size_t)(m_ + sh_)*512 + ii_];    \
                else dst = make_float4(0.f, 0.f, 0.f, 0.f);                    \
            } else {                                                           \
                dst = *(const float4*)&A[(size_t)m_*K + (k0) + ac];            \
            }                                                                  \
        } while (0)

    // prologue: tile 0 into buffer 0
    LOAD_A(0, 0, pa0);
    LOAD_A(0, 64, pa1);
    pb0 = *(const float4*)&Bm[(size_t)br*N + bn + bc];
    pb1 = *(const float4*)&Bm[(size_t)(br+8)*N + bn + bc];
    As[0][ac+0][ar]    = pa0.x; As[0][ac+1][ar]    = pa0.y;
    As[0][ac+2][ar]    = pa0.z; As[0][ac+3][ar]    = pa0.w;
    As[0][ac+0][ar+64] = pa1.x; As[0][ac+1][ar+64] = pa1.y;
    As[0][ac+2][ar+64] = pa1.z; As[0][ac+3][ar+64] = pa1.w;
    *(float4*)&Bs[0][br][bc]   = pb0;
    *(float4*)&Bs[0][br+8][bc] = pb1;
    __syncthreads();

    float acc[8][8] = {};
    int nk = K >> 4;
    int cur = 0;

    for (int kt = 0; kt < nk; kt++) {
        if (kt + 1 < nk) {
            int k0 = (kt + 1) << 4;
            LOAD_A(k0, 0, pa0);
            LOAD_A(k0, 64, pa1);
            pb0 = *(const float4*)&Bm[(size_t)(k0 + br)*N + bn + bc];
            pb1 = *(const float4*)&Bm[(size_t)(k0 + br + 8)*N + bn + bc];
        }
        #pragma unroll
        for (int k = 0; k < 16; k++) {
            float4 a0 = *(const float4*)&As[cur][k][ty << 3];
            float4 a1 = *(const float4*)&As[cur][k][(ty << 3) + 4];
            float4 b0 = *(const float4*)&Bs[cur][k][tx << 3];
            float4 b1 = *(const float4*)&Bs[cur][k][(tx << 3) + 4];
            float a[8] = {a0.x, a0.y, a0.z, a0.w, a1.x, a1.y, a1.z, a1.w};
            float b[8] = {b0.x, b0.y, b0.z, b0.w, b1.x, b1.y, b1.z, b1.w};
            #pragma unroll
            for (int i = 0; i < 8; i++)
                #pragma unroll
                for (int j = 0; j < 8; j++)
                    acc[i][j] += a[i] * b[j];
        }
        if (kt + 1 < nk) {
            int nx = cur ^ 1;
            As[nx][ac+0][ar]    = pa0.x; As[nx][ac+1][ar]    = pa0.y;
            As[nx][ac+2][ar]    = pa0.z; As[nx][ac+3][ar]    = pa0.w;
            As[nx][ac+0][ar+64] = pa1.x; As[nx][ac+1][ar+64] = pa1.y;
            As[nx][ac+2][ar+64] = pa1.z; As[nx][ac+3][ar+64] = pa1.w;
            *(float4*)&Bs[nx][br][bc]   = pb0;
            *(float4*)&Bs[nx][br+8][bc] = pb1;
        }
        __syncthreads();
        cur ^= 1;
    }
    #undef LOAD_A

    // epilogue
    float bb[8];
    *(float4*)&bb[0] = *(const float4*)&bias[bn + (tx << 3)];
    *(float4*)&bb[4] = *(const float4*)&bias[bn + (tx << 3) + 4];
    #pragma unroll
    for (int i = 0; i < 8; i++) {
        int row = bm + (ty << 3) + i;
        float o[8];
        #pragma unroll
        for (int j = 0; j < 8; j++) {
            o[j] = acc[i][j] + bb[j];
            if (RELU) o[j] = fmaxf(o[j], 0.f);
        }
        if (ADDRES) {
            float4 r0 = *(const float4*)&res[(size_t)row*N + bn + (tx << 3)];
            float4 r1 = *(const float4*)&res[(size_t)row*N + bn + (tx << 3) + 4];
            o[0] += r0.x; o[1] += r0.y; o[2] += r0.z; o[3] += r0.w;
            o[4] += r1.x; o[5] += r1.y; o[6] += r1.z; o[7] += r1.w;
        }
        *(float4*)&C[(size_t)row*N + bn + (tx << 3)]     = *(float4*)&o[0];
        *(float4*)&C[(size_t)row*N + bn + (tx << 3) + 4] = *(float4*)&o[4];
    }
}

// ---------------- fused add + LayerNorm ----------------
__global__ __launch_bounds__(256) void ln_kernel(
    const float* __restrict__ a, const float* __restrict__ b,
    const float* __restrict__ sc, const float* __restrict__ bi,
    float* __restrict__ out)
{
    int row = blockIdx.x;
    int t = threadIdx.x;
    const float* ar = a + (size_t)row*ND;
    const float* br = b + (size_t)row*ND;
    float v0 = ar[t]       + br[t];
    float v1 = ar[t + 256] + br[t + 256];
    float s1 = v0 + v1;
    float s2 = v0*v0 + v1*v1;
    #pragma unroll
    for (int off = 16; off > 0; off >>= 1) {
        s1 += __shfl_xor_sync(0xffffffffu, s1, off);
        s2 += __shfl_xor_sync(0xffffffffu, s2, off);
    }
    __shared__ float r1[8], r2[8], mv[2];
    int w = t >> 5, lane = t & 31;
    if (lane == 0) { r1[w] = s1; r2[w] = s2; }
    __syncthreads();
    if (t == 0) {
        float a1 = 0.f, a2 = 0.f;
        #pragma unroll
        for (int i = 0; i < 8; i++) { a1 += r1[i]; a2 += r2[i]; }
        float mean = a1 * (1.f/512.f);
        float var  = a2 * (1.f/512.f) - mean*mean;
        mv[0] = mean;
        mv[1] = rsqrtf(var + 1e-5f);
    }
    __syncthreads();
    float mean = mv[0], rstd = mv[1];
    out[(size_t)row*ND + t]       = (v0 - mean)*rstd*sc[t]       + bi[t];
    out[(size_t)row*ND + t + 256] = (v1 - mean)*rstd*sc[t + 256] + bi[t + 256];
}

// ---------------- scores: per (b,h), lower-triangular 64x64 tiles of q @ k^T * scale --------
__global__ __launch_bounds__(256) void scores_kernel(
    const float* __restrict__ q, const float* __restrict__ k, float* __restrict__ sc)
{
    int nt = blockIdx.x, mt = blockIdx.y, bh = blockIdx.z;
    if (nt > mt) return;
    int b = bh >> 3, h = bh & 7;
    __shared__ float Qs[64*65];
    __shared__ float Ks[64*65];
    int t = threadIdx.x;
    const float* qb = q + ((size_t)(b*NL + mt*64))*ND + h*HD;
    const float* kb = k + ((size_t)(b*NL + nt*64))*ND + h*HD;
    #pragma unroll
    for (int i = 0; i < 16; i++) {
        int lin = t + (i << 8);
        int r = lin >> 6, d = lin & 63;
        Qs[r*65 + d] = qb[(size_t)r*ND + d];
        Ks[r*65 + d] = kb[(size_t)r*ND + d];
    }
    __syncthreads();
    int tx = t & 15, ty = t >> 4;
    float acc[4][4] = {};
    #pragma unroll 4
    for (int d = 0; d < 64; d++) {
        float ar[4], br[4];
        #pragma unroll
        for (int i = 0; i < 4; i++) ar[i] = Qs[((ty<<2)+i)*65 + d];
        #pragma unroll
        for (int j = 0; j < 4; j++) br[j] = Ks[((tx<<2)+j)*65 + d];
        #pragma unroll
        for (int i = 0; i < 4; i++)
            #pragma unroll
            for (int j = 0; j < 4; j++)
                acc[i][j] += ar[i]*br[j];
    }
    float* base = sc + (size_t)bh*NL*NL;
    #pragma unroll
    for (int i = 0; i < 4; i++) {
        int m = mt*64 + (ty<<2) + i;
        float4 o;
        o.x = acc[i][0]*0.125f; o.y = acc[i][1]*0.125f;
        o.z = acc[i][2]*0.125f; o.w = acc[i][3]*0.125f;
        *(float4*)&base[(size_t)m*NL + nt*64 + (tx<<2)] = o;
    }
}

// ---------------- top-k(256) select + softmax + P@V -----------------
// block = (qtile of 32 rows, bh). 256 threads, 8 warps, each warp owns 4 rows.
// dyn smem: p[32][512] (64KB) + vt[64][64] (16KB) = 80KB
__global__ __launch_bounds__(256) void attn_kernel(
    const float* __restrict__ sc, const float* __restrict__ v, float* __restrict__ ao)
{
    extern __shared__ float sm[];
    float* p  = sm;             // 32*512
    float* vt = sm + 32*512;    // 64*64
    int qt = blockIdx.x, bh = blockIdx.y;
    int b = bh >> 3, h = bh & 7;
    int t = threadIdx.x;

    // load 32 score rows
    const float4* s4 = (const float4*)(sc + (size_t)bh*NL*NL + (size_t)(qt*32)*NL);
    float4* p4 = (float4*)p;
    #pragma unroll
    for (int i = 0; i < 16; i++) p4[t + (i << 8)] = s4[t + (i << 8)];
    __syncthreads();

    int w = t >> 5, lane = t & 31;
    for (int rr = 0; rr < 4; rr++) {
        int r  = (w << 2) + rr;
        int qg = (qt << 5) + r;
        int nv = qg + 1;                       // valid prefix length
        float    ev[16];
        unsigned uv[16];
        float    svv[16];
        #pragma unroll
        for (int ii = 0; ii < 16; ii++) {
            int j = lane + (ii << 5);
            bool val = j < nv;
            float s = val ? p[(r << 9) + j] : NEGINF;
            svv[ii] = s;
            unsigned bits = __float_as_uint(s);
            uv[ii] = val ? ((bits & 0x80000000u) ? ~bits : (bits | 0x80000000u)) : 0u;
        }
        unsigned T = 1u;                       // nv<=256: keep every valid element
        if (nv > 256) {
            T = 0u;
            for (int bit = 31; bit >= 0; bit--) {
                unsigned cand = T | (1u << bit);
                int c = 0;
                #pragma unroll
                for (int ii = 0; ii < 16; ii++) c += (uv[ii] >= cand);
                c = __reduce_add_sync(0xffffffffu, c);
                if (c >= 256) T = cand;
            }
        }
        float m = NEGINF;
        #pragma unroll
        for (int ii = 0; ii < 16; ii++)
            if (uv[ii] >= T) m = fmaxf(m, svv[ii]);
        #pragma unroll
        for (int off = 16; off > 0; off >>= 1)
            m = fmaxf(m, __shfl_xor_sync(0xffffffffu, m, off));
        float z = 0.f;
        #pragma unroll
        for (int ii = 0; ii < 16; ii++) {
            float e = (uv[ii] >= T) ? __expf(svv[ii] - m) : 0.f;
            ev[ii] = e;
            z += e;
        }
        #pragma unroll
        for (int off = 16; off > 0; off >>= 1)
            z += __shfl_xor_sync(0xffffffffu, z, off);
        float inv = 1.f / z;
        #pragma unroll
        for (int ii = 0; ii < 16; ii++) {
            int j = lane + (ii << 5);
            p[(r << 9) + j] = ev[ii] * inv;
        }
    }
    __syncthreads();

    // P @ V
    float acc[8] = {};
    int d = t & 63, rb = t >> 6;
    for (int jt = 0; jt < 8; jt++) {
        const float4* v4 = (const float4*)(v + ((size_t)(b*NL + (jt << 6)))*ND + (h << 6));
        float4* vt4 = (float4*)vt;
        #pragma unroll
        for (int i = 0; i < 4; i++) {
            int lin = t + (i << 8);           // 0..1023 float4s
            int jr = lin >> 4, d4 = lin & 15;
            vt4[lin] = v4[(size_t)jr*128 + d4];
        }
        __syncthreads();
        #pragma unroll 2
        for (int j = 0; j < 64; j++) {
            float vv = vt[(j << 6) + d];
            int jj = (jt << 6) + j;
            #pragma unroll
            for (int i = 0; i < 8; i++)
                acc[i] += p[((rb + (i << 2)) << 9) + jj] * vv;
        }
        __syncthreads();
    }
    #pragma unroll
    for (int i = 0; i < 8; i++) {
        int row = (qt << 5) + rb + (i << 2);
        ao[((size_t)(b*NL + row))*ND + (h << 6) + d] = acc[i];
    }
}

// ---------------- launch ----------------
extern "C" void kernel_launch(void* const* d_in, const int* in_sizes, int n_in,
                              void* d_out, int out_size) {
    const float* x     = (const float*)d_in[0];
    const float* tf    = (const float*)d_in[1];
    const float* in_w  = (const float*)d_in[2];
    const float* in_b  = (const float*)d_in[3];
    const float* pe    = (const float*)d_in[4];
    const float* tw    = (const float*)d_in[5];
    const float* tb    = (const float*)d_in[6];
    const float* ps    = (const float*)d_in[7];
    const float* ts    = (const float*)d_in[8];
    const float* convw = (const float*)d_in[9];
    const float* convb = (const float*)d_in[10];
    const float* qw    = (const float*)d_in[11];
    const float* qb    = (const float*)d_in[12];
    const float* kw    = (const float*)d_in[13];
    const float* kb    = (const float*)d_in[14];
    const float* vw    = (const float*)d_in[15];
    const float* vb    = (const float*)d_in[16];
    const float* ow    = (const float*)d_in[17];
    const float* ob    = (const float*)d_in[18];
    const float* f1w   = (const float*)d_in[19];
    const float* f1b   = (const float*)d_in[20];
    const float* f2w   = (const float*)d_in[21];
    const float* f2b   = (const float*)d_in[22];
    const float* n1s   = (const float*)d_in[23];
    const float* n1b   = (const float*)d_in[24];
    const float* n2s   = (const float*)d_in[25];
    const float* n2b   = (const float*)d_in[26];

    float *h, *tbuf, *qv, *kv, *vv, *ao, *mid, *sc, *cw;
    cudaGetSymbolAddress((void**)&h,    g_h);
    cudaGetSymbolAddress((void**)&tbuf, g_t);
    cudaGetSymbolAddress((void**)&qv,   g_q);
    cudaGetSymbolAddress((void**)&kv,   g_k);
    cudaGetSymbolAddress((void**)&vv,   g_v);
    cudaGetSymbolAddress((void**)&ao,   g_ao);
    cudaGetSymbolAddress((void**)&mid,  g_mid);
    cudaGetSymbolAddress((void**)&sc,   g_sc);
    cudaGetSymbolAddress((void**)&cw,   g_cw);

    cudaFuncSetAttribute(attn_kernel, cudaFuncAttributeMaxDynamicSharedMemorySize, 81920);

    // conv weight re-layout (deterministic each call)
    tconv_kernel<<<(NE*3*ND*ND)/256, 256>>>(convw, cw);

    // input embedding
    embed_kernel<<<NBL, 256>>>(x, tf, in_w, in_b, pe, tw, tb, ps, ts, h);

    dim3 g512(ND/128, NBL/128);     // N=512  -> (4, 32)
    dim3 gdf (NDF/128, NBL/128);    // N=2048 -> (16, 32)

    for (int l = 0; l < NE; l++) {
        // causal conv (K = 3*512 = 1536) -> tbuf, then LN1 -> h
        gemm_kernel<1,0,0><<<g512, 256>>>(h, cw + (size_t)l*3*ND*ND, convb + l*ND,
                                          nullptr, tbuf, ND, 3*ND);
        ln_kernel<<<NBL, 256>>>(h, tbuf, n1s + l*ND, n1b + l*ND, h);

        // Q, K, V projections
        gemm_kernel<0,0,0><<<g512, 256>>>(h, qw + (size_t)l*ND*ND, qb + l*ND, nullptr, qv, ND, ND);
        gemm_kernel<0,0,0><<<g512, 256>>>(h, kw + (size_t)l*ND*ND, kb + l*ND, nullptr, kv, ND, ND);
        gemm_kernel<0,0,0><<<g512, 256>>>(h, vw + (size_t)l*ND*ND, vb + l*ND, nullptr, vv, ND, ND);

        // scores (lower-triangular tiles only)
        scores_kernel<<<dim3(8, 8, 64), 256>>>(qv, kv, sc);

        // top-k select + softmax + P@V
        attn_kernel<<<dim3(16, 64), 256, 81920>>>(sc, vv, ao);

        // output projection -> tbuf, LN2 -> h
        gemm_kernel<0,0,0><<<g512, 256>>>(ao, ow + (size_t)l*ND*ND, ob + l*ND, nullptr, tbuf, ND, ND);
        ln_kernel<<<NBL, 256>>>(h, tbuf, n2s + l*ND, n2b + l*ND, h);

        // FFN
        gemm_kernel<0,1,0><<<gdf, 256>>>(h, f1w + (size_t)l*ND*NDF, f1b + l*NDF,
                                         nullptr, mid, NDF, ND);
        float* outp = (l == NE-1) ? (float*)d_out : h;
        gemm_kernel<0,0,1><<<g512, 256>>>(mid, f2w + (size_t)l*NDF*ND, f2b + l*ND,
                                          h, outp, ND, NDF);
    }
}